// round 11
// baseline (speedup 1.0000x reference)
#include <cuda_runtime.h>
#include <cuda_bf16.h>
#include <math.h>

#define S_ 512
#define B_ 8
#define D_ 512
#define H_ 8
#define HD_ 64
#define E_ 4
#define L_ 6
#define FF_ 2048
#define V_ 32000
#define N_ 4096
#define EPS_ 1e-5f
#define NEGINF_ (-3.402823466e38f)

// ---------------- scratch (static device globals; no allocation) ----------------
__device__ float g_x[N_*D_];
__device__ float g_tmp[N_*D_];
__device__ float g_q[E_*N_*D_];
__device__ float g_k[E_*N_*D_];
__device__ float g_v[E_*N_*D_];
__device__ float g_ctx[E_*N_*D_];
__device__ float g_h[N_*FF_];
__device__ float g_gate[N_*E_];
__device__ float g_aux;

// converted weights: [M][K] bf16, hi/lo split
__device__ __nv_bfloat16 g_wq_h[L_*E_*D_*D_], g_wq_l[L_*E_*D_*D_];
__device__ __nv_bfloat16 g_wk_h[L_*E_*D_*D_], g_wk_l[L_*E_*D_*D_];
__device__ __nv_bfloat16 g_wv_h[L_*E_*D_*D_], g_wv_l[L_*E_*D_*D_];
__device__ __nv_bfloat16 g_wo_h[L_*E_*D_*D_], g_wo_l[L_*E_*D_*D_];
__device__ __nv_bfloat16 g_w1_h[L_*D_*FF_],   g_w1_l[L_*D_*FF_];
__device__ __nv_bfloat16 g_w2_h[L_*FF_*D_],   g_w2_l[L_*FF_*D_];
__device__ __nv_bfloat16 g_ow_h[(size_t)D_*V_], g_ow_l[(size_t)D_*V_];

// ---------------- asm helpers ----------------
__device__ __forceinline__ void ldsm4(unsigned* r, unsigned addr)
{
    asm volatile(
        "ldmatrix.sync.aligned.m8n8.x4.shared.b16 {%0,%1,%2,%3}, [%4];"
        : "=r"(r[0]), "=r"(r[1]), "=r"(r[2]), "=r"(r[3])
        : "r"(addr));
}

__device__ __forceinline__ void mma16816(float* d, const unsigned* a, unsigned b0, unsigned b1)
{
    asm volatile(
        "mma.sync.aligned.m16n8k16.row.col.f32.bf16.bf16.f32 "
        "{%0,%1,%2,%3},{%4,%5,%6,%7},{%8,%9},{%0,%1,%2,%3};"
        : "+f"(d[0]), "+f"(d[1]), "+f"(d[2]), "+f"(d[3])
        : "r"(a[0]), "r"(a[1]), "r"(a[2]), "r"(a[3]), "r"(b0), "r"(b1));
}

// ---------------- weight convert: W[K][M] fp32 -> Hi/Lo[M][K] bf16 ----------------
__global__ __launch_bounds__(256) void convert_w(
    const float* __restrict__ W, __nv_bfloat16* __restrict__ Hi,
    __nv_bfloat16* __restrict__ Lo, int K, int M, size_t inz, size_t outz)
{
    W  += (size_t)blockIdx.z * inz;
    Hi += (size_t)blockIdx.z * outz;
    Lo += (size_t)blockIdx.z * outz;
    __shared__ float tile[32][33];
    int m0 = blockIdx.x * 32, k0 = blockIdx.y * 32;
    int tx = threadIdx.x & 31, ty = threadIdx.x >> 5;
    #pragma unroll
    for (int i = 0; i < 32; i += 8)
        tile[ty + i][tx] = W[(size_t)(k0 + ty + i) * M + m0 + tx];
    __syncthreads();
    #pragma unroll
    for (int i = 0; i < 32; i += 8) {
        float v = tile[tx][ty + i];
        __nv_bfloat16 h = __float2bfloat16(v);
        float r = v - __bfloat162float(h);
        size_t o = (size_t)(m0 + ty + i) * K + k0 + tx;
        Hi[o] = h;
        Lo[o] = __float2bfloat16(r);
    }
}

// ---------------- embed + positional encoding (+ zero aux) ----------------
__global__ void embed_kernel(const int* __restrict__ src, const float* __restrict__ emb)
{
    int n = blockIdx.x;
    int s = n / B_;
    if (n == 0 && threadIdx.x == 0) g_aux = 0.f;
    int tok = src[n];
    const float scale = 22.62741699796952f;
    for (int d = threadIdx.x; d < D_; d += blockDim.x) {
        int j = d >> 1;
        float div = expf((float)(2*j) * (-9.210340371976184f / (float)D_));
        float ang = (float)s * div;
        float pe = (d & 1) ? cosf(ang) : sinf(ang);
        g_x[(size_t)n*D_ + d] = emb[(size_t)tok*D_ + d] * scale + pe;
    }
}

// ---------------- gate ----------------
__global__ void gate_kernel(const float* __restrict__ gw, const float* __restrict__ gb)
{
    int n = blockIdx.x;
    int t = threadIdx.x;
    float p0=0.f, p1=0.f, p2=0.f, p3=0.f;
    for (int d = t; d < D_; d += 128) {
        float xv = g_x[(size_t)n*D_ + d];
        const float* w = gw + (size_t)d*E_;
        p0 = fmaf(xv, w[0], p0);
        p1 = fmaf(xv, w[1], p1);
        p2 = fmaf(xv, w[2], p2);
        p3 = fmaf(xv, w[3], p3);
    }
    __shared__ float red[4][128];
    red[0][t]=p0; red[1][t]=p1; red[2][t]=p2; red[3][t]=p3;
    __syncthreads();
    for (int off = 64; off > 0; off >>= 1) {
        if (t < off) {
            red[0][t]+=red[0][t+off]; red[1][t]+=red[1][t+off];
            red[2][t]+=red[2][t+off]; red[3][t]+=red[3][t+off];
        }
        __syncthreads();
    }
    if (t == 0) {
        float l0=red[0][0]+gb[0], l1=red[1][0]+gb[1], l2=red[2][0]+gb[2], l3=red[3][0]+gb[3];
        float mx = fmaxf(fmaxf(l0,l1), fmaxf(l2,l3));
        float e0=expf(l0-mx), e1=expf(l1-mx), e2=expf(l2-mx), e3=expf(l3-mx);
        float inv = 1.f / (e0+e1+e2+e3);
        g_gate[n*4+0]=e0*inv; g_gate[n*4+1]=e1*inv; g_gate[n*4+2]=e2*inv; g_gate[n*4+3]=e3*inv;
    }
}

// ---------------- aux loss ----------------
__global__ void aux_kernel()
{
    __shared__ float red[4][256];
    int t = threadIdx.x;
    float p0=0.f, p1=0.f, p2=0.f, p3=0.f;
    for (int n = t; n < N_; n += 256) {
        p0+=g_gate[n*4+0]; p1+=g_gate[n*4+1];
        p2+=g_gate[n*4+2]; p3+=g_gate[n*4+3];
    }
    red[0][t]=p0; red[1][t]=p1; red[2][t]=p2; red[3][t]=p3;
    __syncthreads();
    for (int off = 128; off > 0; off >>= 1) {
        if (t < off) {
            red[0][t]+=red[0][t+off]; red[1][t]+=red[1][t+off];
            red[2][t]+=red[2][t+off]; red[3][t]+=red[3][t+off];
        }
        __syncthreads();
    }
    if (t == 0) {
        float i0=red[0][0], i1=red[1][0], i2=red[2][0], i3=red[3][0];
        float mean = (i0+i1+i2+i3)*0.25f;
        float d0=i0-mean, d1=i1-mean, d2=i2-mean, d3=i3-mean;
        float var = (d0*d0+d1*d1+d2*d2+d3*d3)*0.25f;
        g_aux += var / (mean*mean + 1e-10f);
    }
}

// ---------------- tensor-core GEMM: 128x128 tile, in-kernel A split ---------------
// C = A(fp32 [N][K]) @ W(split-bf16 [M][K]) + bias. 256 threads (8 warps 4x2).
// Per warp: 32 rows x 128 cols. Split-bf16: Ah*Wh + Ah*Wl + Al*Wh.
#define APITCH 40

__global__ __launch_bounds__(256) void gemm_mma(
    const float* __restrict__ A,
    const __nv_bfloat16* __restrict__ Wh, const __nv_bfloat16* __restrict__ Wl,
    const float* __restrict__ bias, float* __restrict__ C,
    int N, int K, int M,
    size_t az, size_t wz, size_t bz, size_t cz, int relu)
{
    A    += (size_t)blockIdx.z * az;
    Wh   += (size_t)blockIdx.z * wz;
    Wl   += (size_t)blockIdx.z * wz;
    bias += (size_t)blockIdx.z * bz;
    C    += (size_t)blockIdx.z * cz;

    __shared__ __nv_bfloat16 sAh[128*APITCH];
    __shared__ __nv_bfloat16 sAl[128*APITCH];
    __shared__ __nv_bfloat16 sBh[128*APITCH];
    __shared__ __nv_bfloat16 sBl[128*APITCH];

    const int t = threadIdx.x;
    const int lane = t & 31;
    const int wid = t >> 5;
    const int n0 = blockIdx.y * 128;     // rows
    const int m0 = blockIdx.x * 128;     // cols
    const int wm = (wid >> 1) * 32;      // warp row offset (4 groups)
    const int wn = (wid & 1) * 64;       // warp col offset (2 groups)

    const int lrow = lane & 15;
    const int lk = (lane >> 4) * 8;
    const unsigned aBaseH = (unsigned)__cvta_generic_to_shared(sAh) + (unsigned)(((wm + lrow)*APITCH + lk)*2);
    const unsigned aBaseL = (unsigned)__cvta_generic_to_shared(sAl) + (unsigned)(((wm + lrow)*APITCH + lk)*2);
    const unsigned bBaseH = (unsigned)__cvta_generic_to_shared(sBh) + (unsigned)(((wn + lrow)*APITCH + lk)*2);
    const unsigned bBaseL = (unsigned)__cvta_generic_to_shared(sBl) + (unsigned)(((wn + lrow)*APITCH + lk)*2);

    float acc[2][8][4];
    #pragma unroll
    for (int i = 0; i < 2; i++) {
        #pragma unroll
        for (int j = 0; j < 8; j++) {
            #pragma unroll
            for (int c = 0; c < 4; c++) {
                acc[i][j][c] = 0.f;
            }
        }
    }

    const int brow = t >> 1;           // 128 rows, 2 threads/row
    const int bch = (t & 1) * 16;      // 2 chunks of 16 bf16

    for (int k0 = 0; k0 < K; k0 += 32) {
        // A tile 128x32 fp32 -> hi/lo bf16 (1024 float4 slots / 256 threads)
        #pragma unroll
        for (int i = 0; i < 4; i++) {
            int idx = t + i*256;
            int row = idx >> 3;
            int kq = (idx & 7) * 4;
            float4 v = *(const float4*)(A + (size_t)(n0+row)*K + k0 + kq);
            __nv_bfloat16 h0 = __float2bfloat16(v.x);
            __nv_bfloat16 h1 = __float2bfloat16(v.y);
            __nv_bfloat16 h2 = __float2bfloat16(v.z);
            __nv_bfloat16 h3 = __float2bfloat16(v.w);
            __nv_bfloat16 e0 = __float2bfloat16(v.x - __bfloat162float(h0));
            __nv_bfloat16 e1 = __float2bfloat16(v.y - __bfloat162float(h1));
            __nv_bfloat16 e2 = __float2bfloat16(v.z - __bfloat162float(h2));
            __nv_bfloat16 e3 = __float2bfloat16(v.w - __bfloat162float(h3));
            __nv_bfloat162* ph = (__nv_bfloat162*)(sAh + row*APITCH + kq);
            __nv_bfloat162* pl = (__nv_bfloat162*)(sAl + row*APITCH + kq);
            ph[0] = __halves2bfloat162(h0, h1);
            ph[1] = __halves2bfloat162(h2, h3);
            pl[0] = __halves2bfloat162(e0, e1);
            pl[1] = __halves2bfloat162(e2, e3);
        }
        // B tile 128x32 bf16 hi/lo (each thread: 16 bf16 = 2x16B per part)
        {
            const __nv_bfloat16* gh = Wh + (size_t)(m0+brow)*K + k0 + bch;
            const __nv_bfloat16* gl = Wl + (size_t)(m0+brow)*K + k0 + bch;
            uint4 vh0 = *(const uint4*)gh;
            uint4 vh1 = *(const uint4*)(gh + 8);
            uint4 vl0 = *(const uint4*)gl;
            uint4 vl1 = *(const uint4*)(gl + 8);
            *(uint4*)(sBh + brow*APITCH + bch)     = vh0;
            *(uint4*)(sBh + brow*APITCH + bch + 8) = vh1;
            *(uint4*)(sBl + brow*APITCH + bch)     = vl0;
            *(uint4*)(sBl + brow*APITCH + bch + 8) = vl1;
        }
        __syncthreads();

        #pragma unroll
        for (int ks = 0; ks < 2; ks++) {
            unsigned ko = (unsigned)(ks * 32);
            unsigned aH[2][4];
            unsigned aL[2][4];
            ldsm4(aH[0], aBaseH + ko);
            ldsm4(aH[1], aBaseH + 1280u + ko);
            ldsm4(aL[0], aBaseL + ko);
            ldsm4(aL[1], aBaseL + 1280u + ko);
            #pragma unroll
            for (int np = 0; np < 4; np++) {
                unsigned bH[4];
                unsigned bL[4];
                ldsm4(bH, bBaseH + (unsigned)(np*1280) + ko);
                ldsm4(bL, bBaseL + (unsigned)(np*1280) + ko);
                #pragma unroll
                for (int mt = 0; mt < 2; mt++) {
                    #pragma unroll
                    for (int sub = 0; sub < 2; sub++) {
                        float* d = acc[mt][np*2 + sub];
                        mma16816(d, aH[mt], bH[sub], bH[sub+2]);
                        mma16816(d, aH[mt], bL[sub], bL[sub+2]);
                        mma16816(d, aL[mt], bH[sub], bH[sub+2]);
                    }
                }
            }
        }
        __syncthreads();
    }

    const int gr = lane >> 2;
    const int q = lane & 3;
    #pragma unroll
    for (int mt = 0; mt < 2; mt++) {
        int row = n0 + wm + mt*16 + gr;
        #pragma unroll
        for (int nt = 0; nt < 8; nt++) {
            int col = m0 + wn + nt*8 + q*2;
            float bx = bias[col];
            float by = bias[col+1];
            float c0 = acc[mt][nt][0] + bx;
            float c1 = acc[mt][nt][1] + by;
            float c2 = acc[mt][nt][2] + bx;
            float c3 = acc[mt][nt][3] + by;
            if (relu) {
                c0 = fmaxf(c0, 0.f); c1 = fmaxf(c1, 0.f);
                c2 = fmaxf(c2, 0.f); c3 = fmaxf(c3, 0.f);
            }
            *(float2*)(C + (size_t)row*M + col)     = make_float2(c0, c1);
            *(float2*)(C + (size_t)(row+8)*M + col) = make_float2(c2, c3);
        }
    }
}

// ---------------- causal attention per (b,e,h): chunked online softmax (R5) -------
__global__ __launch_bounds__(128) void attn_kernel()
{
    int qc  = blockIdx.x;
    int beh = blockIdx.y;
    int h = beh & 7;
    int e = (beh >> 3) & 3;
    int b = beh >> 5;
    int t = threadIdx.x;
    int s = qc*128 + t;

    __shared__ float4 Ks[64][16];
    __shared__ float4 Vs[64][16];

    size_t base = (size_t)e*N_*D_ + (size_t)h*HD_;
    const float* qp = g_q + base + (size_t)(s*B_+b)*D_;

    float4 q4[16];
    #pragma unroll
    for (int i = 0; i < 16; i++) q4[i] = *(const float4*)(qp + i*4);

    float4 a4[16];
    #pragma unroll
    for (int i = 0; i < 16; i++) a4[i] = make_float4(0.f, 0.f, 0.f, 0.f);
    float m = NEGINF_, lsum = 0.f;

    int nkc = 2*qc + 2;
    for (int kc = 0; kc < nkc; kc++) {
        int j0 = kc * 64;
        __syncthreads();
        #pragma unroll
        for (int i = 0; i < 8; i++) {
            int idx = t + i*128;
            int j = idx >> 4;
            int cc = idx & 15;
            size_t off = base + (size_t)((j0+j)*B_ + b)*D_ + cc*4;
            Ks[j][cc] = *(const float4*)(g_k + off);
            Vs[j][cc] = *(const float4*)(g_v + off);
        }
        __syncthreads();
        for (int sub = 0; sub < 4; sub++) {
            int j0s = j0 + sub*16;
            if (j0s > s) break;
            float sc[16];
            #pragma unroll
            for (int jj = 0; jj < 16; jj++) {
                int j = sub*16 + jj;
                float s0=0.f, s1=0.f, s2=0.f, s3=0.f;
                #pragma unroll
                for (int i = 0; i < 16; i++) {
                    float4 kk = Ks[j][i];
                    s0 = fmaf(q4[i].x, kk.x, s0);
                    s1 = fmaf(q4[i].y, kk.y, s1);
                    s2 = fmaf(q4[i].z, kk.z, s2);
                    s3 = fmaf(q4[i].w, kk.w, s3);
                }
                float v = ((s0+s1)+(s2+s3)) * 0.125f;
                sc[jj] = (j0s + jj <= s) ? v : NEGINF_;
            }
            float cm = sc[0];
            #pragma unroll
            for (int jj = 1; jj < 16; jj++) cm = fmaxf(cm, sc[jj]);
            float newm = fmaxf(m, cm);
            float alpha = __expf(m - newm);
            lsum *= alpha;
            #pragma unroll
            for (int i = 0; i < 16; i++) {
                a4[i].x *= alpha; a4[i].y *= alpha;
                a4[i].z *= alpha; a4[i].w *= alpha;
            }
            m = newm;
            #pragma unroll
            for (int jj = 0; jj < 16; jj++) {
                float p = __expf(sc[jj] - m);
                lsum += p;
                int j = sub*16 + jj;
                #pragma unroll
                for (int i = 0; i < 16; i++) {
                    float4 vv = Vs[j][i];
                    a4[i].x = fmaf(p, vv.x, a4[i].x);
                    a4[i].y = fmaf(p, vv.y, a4[i].y);
                    a4[i].z = fmaf(p, vv.z, a4[i].z);
                    a4[i].w = fmaf(p, vv.w, a4[i].w);
                }
            }
        }
    }
    float inv = 1.f / lsum;
    float* op = g_ctx + base + (size_t)(s*B_+b)*D_;
    #pragma unroll
    for (int i = 0; i < 16; i++) {
        float4 o = make_float4(a4[i].x*inv, a4[i].y*inv, a4[i].z*inv, a4[i].w*inv);
        *(float4*)(op + i*4) = o;
    }
}

// ---------------- gate-weighted expert combine ----------------
__global__ void combine_kernel()
{
    int idx = blockIdx.x*256 + threadIdx.x;
    int n = idx >> 7;
    const float4* eo = (const float4*)g_q;
    const int z = N_*D_/4;
    float g0 = g_gate[n*4+0];
    float g1 = g_gate[n*4+1];
    float g2 = g_gate[n*4+2];
    float g3 = g_gate[n*4+3];
    float4 v0 = eo[idx];
    float4 v1 = eo[z+idx];
    float4 v2 = eo[2*z+idx];
    float4 v3 = eo[3*z+idx];
    float4 r;
    r.x = g0*v0.x + g1*v1.x + g2*v2.x + g3*v3.x;
    r.y = g0*v0.y + g1*v1.y + g2*v2.y + g3*v3.y;
    r.z = g0*v0.z + g1*v1.z + g2*v2.z + g3*v3.z;
    r.w = g0*v0.w + g1*v1.w + g2*v2.w + g3*v3.w;
    ((float4*)g_tmp)[idx] = r;
}

// ---------------- LayerNorm ----------------
__device__ __forceinline__ float blocksum128(float v)
{
    __shared__ float sh[4];
    #pragma unroll
    for (int o = 16; o > 0; o >>= 1) v += __shfl_down_sync(0xffffffffu, v, o);
    __syncthreads();
    if ((threadIdx.x & 31) == 0) sh[threadIdx.x >> 5] = v;
    __syncthreads();
    return sh[0] + sh[1] + sh[2] + sh[3];
}

__global__ void ln_kernel(const float* __restrict__ xin, const float* __restrict__ res,
                          const float* __restrict__ g, const float* __restrict__ bb,
                          float* __restrict__ out)
{
    int n = blockIdx.x;
    int t = threadIdx.x;
    float4 v = ((const float4*)(xin + (size_t)n*D_))[t];
    if (res) {
        float4 r = ((const float4*)(res + (size_t)n*D_))[t];
        v.x += r.x; v.y += r.y; v.z += r.z; v.w += r.w;
    }
    float mean = blocksum128(v.x+v.y+v.z+v.w) * (1.f/D_);
    float d0 = v.x-mean, d1 = v.y-mean, d2 = v.z-mean, d3 = v.w-mean;
    float var = blocksum128(d0*d0 + d1*d1 + d2*d2 + d3*d3) * (1.f/D_);
    float rstd = rsqrtf(var + EPS_);
    float4 gg = ((const float4*)g)[t];
    float4 bv = ((const float4*)bb)[t];
    float4 o;
    o.x = d0*rstd*gg.x + bv.x;
    o.y = d1*rstd*gg.y + bv.y;
    o.z = d2*rstd*gg.z + bv.z;
    o.w = d3*rstd*gg.w + bv.w;
    ((float4*)(out + (size_t)n*D_))[t] = o;
}

// ---------------- in-place log_softmax over V per row ----------------
__global__ void lsm_kernel(float* __restrict__ out)
{
    __shared__ float sh[8];
    int n = blockIdx.x;
    int t = threadIdx.x;
    float* row = out + (size_t)n*V_;
    float mx = NEGINF_;
    for (int v = t; v < V_; v += 256) mx = fmaxf(mx, row[v]);
    #pragma unroll
    for (int o = 16; o > 0; o >>= 1) mx = fmaxf(mx, __shfl_xor_sync(0xffffffffu, mx, o));
    if ((t & 31) == 0) sh[t >> 5] = mx;
    __syncthreads();
    mx = fmaxf(fmaxf(fmaxf(sh[0],sh[1]), fmaxf(sh[2],sh[3])),
               fmaxf(fmaxf(sh[4],sh[5]), fmaxf(sh[6],sh[7])));
    float sum = 0.f;
    for (int v = t; v < V_; v += 256) sum += expf(row[v] - mx);
    #pragma unroll
    for (int o = 16; o > 0; o >>= 1) sum += __shfl_xor_sync(0xffffffffu, sum, o);
    __syncthreads();
    if ((t & 31) == 0) sh[t >> 5] = sum;
    __syncthreads();
    sum = ((sh[0]+sh[1]) + (sh[2]+sh[3])) + ((sh[4]+sh[5]) + (sh[6]+sh[7]));
    float lse = mx + logf(sum);
    for (int v = t; v < V_; v += 256) row[v] -= lse;
}

__global__ void write_aux_kernel(float* __restrict__ out)
{
    out[(size_t)N_*V_] = g_aux;
}

// ---------------- host orchestration ----------------
extern "C" void kernel_launch(void* const* d_in, const int* in_sizes, int n_in,
                              void* d_out, int out_size)
{
    (void)in_sizes; (void)n_in;
    const int*   src    = (const int*)  d_in[1];
    const float* emb    = (const float*)d_in[2];
    const float* gate_w = (const float*)d_in[3];
    const float* gate_b = (const float*)d_in[4];
    const float* wq     = (const float*)d_in[5];
    const float* wk     = (const float*)d_in[6];
    const float* wv     = (const float*)d_in[7];
    const float* wo     = (const float*)d_in[8];
    const float* bq     = (const float*)d_in[9];
    const float* bk     = (const float*)d_in[10];
    const float* bv     = (const float*)d_in[11];
    const float* bo     = (const float*)d_in[12];
    const float* w1     = (const float*)d_in[13];
    const float* b1     = (const float*)d_in[14];
    const float* w2     = (const float*)d_in[15];
    const float* b2     = (const float*)d_in[16];
    const float* ln1_g  = (const float*)d_in[17];
    const float* ln1_b  = (const float*)d_in[18];
    const float* ln2_g  = (const float*)d_in[19];
    const float* ln2_b  = (const float*)d_in[20];
    const float* ln3_g  = (const float*)d_in[21];
    const float* ln3_b  = (const float*)d_in[22];
    const float* lnf_g  = (const float*)d_in[23];
    const float* lnf_b  = (const float*)d_in[24];
    const float* out_w  = (const float*)d_in[25];
    const float* out_b  = (const float*)d_in[26];
    float* out = (float*)d_out;

    float *px, *ptmp, *pq, *pk, *pv, *pctx, *ph;
    cudaGetSymbolAddress((void**)&px,   g_x);
    cudaGetSymbolAddress((void**)&ptmp, g_tmp);
    cudaGetSymbolAddress((void**)&pq,   g_q);
    cudaGetSymbolAddress((void**)&pk,   g_k);
    cudaGetSymbolAddress((void**)&pv,   g_v);
    cudaGetSymbolAddress((void**)&pctx, g_ctx);
    cudaGetSymbolAddress((void**)&ph,   g_h);

    __nv_bfloat16 *pwq_h, *pwq_l, *pwk_h, *pwk_l, *pwv_h, *pwv_l, *pwo_h, *pwo_l;
    __nv_bfloat16 *pw1_h, *pw1_l, *pw2_h, *pw2_l, *pow_h, *pow_l;
    cudaGetSymbolAddress((void**)&pwq_h, g_wq_h);
    cudaGetSymbolAddress((void**)&pwq_l, g_wq_l);
    cudaGetSymbolAddress((void**)&pwk_h, g_wk_h);
    cudaGetSymbolAddress((void**)&pwk_l, g_wk_l);
    cudaGetSymbolAddress((void**)&pwv_h, g_wv_h);
    cudaGetSymbolAddress((void**)&pwv_l, g_wv_l);
    cudaGetSymbolAddress((void**)&pwo_h, g_wo_h);
    cudaGetSymbolAddress((void**)&pwo_l, g_wo_l);
    cudaGetSymbolAddress((void**)&pw1_h, g_w1_h);
    cudaGetSymbolAddress((void**)&pw1_l, g_w1_l);
    cudaGetSymbolAddress((void**)&pw2_h, g_w2_h);
    cudaGetSymbolAddress((void**)&pw2_l, g_w2_l);
    cudaGetSymbolAddress((void**)&pow_h, g_ow_h);
    cudaGetSymbolAddress((void**)&pow_l, g_ow_l);

    size_t dd = (size_t)D_*D_;
    size_t nd = (size_t)N_*D_;

    convert_w<<<dim3(D_/32, D_/32, L_*E_), 256>>>(wq, pwq_h, pwq_l, D_, D_, dd, dd);
    convert_w<<<dim3(D_/32, D_/32, L_*E_), 256>>>(wk, pwk_h, pwk_l, D_, D_, dd, dd);
    convert_w<<<dim3(D_/32, D_/32, L_*E_), 256>>>(wv, pwv_h, pwv_l, D_, D_, dd, dd);
    convert_w<<<dim3(D_/32, D_/32, L_*E_), 256>>>(wo, pwo_h, pwo_l, D_, D_, dd, dd);
    convert_w<<<dim3(FF_/32, D_/32, L_), 256>>>(w1, pw1_h, pw1_l, D_, FF_, (size_t)D_*FF_, (size_t)D_*FF_);
    convert_w<<<dim3(D_/32, FF_/32, L_), 256>>>(w2, pw2_h, pw2_l, FF_, D_, (size_t)FF_*D_, (size_t)FF_*D_);
    convert_w<<<dim3(V_/32, D_/32, 1), 256>>>(out_w, pow_h, pow_l, D_, V_, 0, 0);

    embed_kernel<<<N_, 128>>>(src, emb);

    for (int l = 0; l < L_; l++) {
        gate_kernel<<<N_, 128>>>(gate_w + (size_t)l*D_*E_, gate_b + (size_t)l*E_);
        aux_kernel<<<1, 256>>>();

        dim3 gqkv(D_/128, N_/128, E_);
        size_t woff = (size_t)l*E_*dd;
        size_t boff = (size_t)l*E_*D_;
        gemm_mma<<<gqkv, 256>>>(px, pwq_h + woff, pwq_l + woff, bq + boff, pq,
                                N_, D_, D_, 0, dd, D_, nd, 0);
        gemm_mma<<<gqkv, 256>>>(px, pwk_h + woff, pwk_l + woff, bk + boff, pk,
                                N_, D_, D_, 0, dd, D_, nd, 0);
        gemm_mma<<<gqkv, 256>>>(px, pwv_h + woff, pwv_l + woff, bv + boff, pv,
                                N_, D_, D_, 0, dd, D_, nd, 0);

        attn_kernel<<<dim3(4, B_*E_*H_), 128>>>();

        gemm_mma<<<gqkv, 256>>>(pctx, pwo_h + woff, pwo_l + woff, bo + boff, pq,
                                N_, D_, D_, nd, dd, D_, nd, 0);

        combine_kernel<<<(N_*D_/4)/256, 256>>>();

        ln_kernel<<<N_, 128>>>(px, ptmp, ln1_g + (size_t)l*D_, ln1_b + (size_t)l*D_, px);
        ln_kernel<<<N_, 128>>>(px, (const float*)0, ln2_g + (size_t)l*D_, ln2_b + (size_t)l*D_, px);

        gemm_mma<<<dim3(FF_/128, N_/128), 256>>>(px, pw1_h + (size_t)l*D_*FF_, pw1_l + (size_t)l*D_*FF_,
                                                 b1 + (size_t)l*FF_, ph, N_, D_, FF_, 0, 0, 0, 0, 1);
        gemm_mma<<<dim3(D_/128, N_/128), 256>>>(ph, pw2_h + (size_t)l*FF_*D_, pw2_l + (size_t)l*FF_*D_,
                                                b2 + (size_t)l*D_, ptmp, N_, FF_, D_, 0, 0, 0, 0, 0);

        ln_kernel<<<N_, 128>>>(px, ptmp, ln3_g + (size_t)l*D_, ln3_b + (size_t)l*D_, px);
    }

    ln_kernel<<<N_, 128>>>(px, (const float*)0, lnf_g, lnf_b, px);

    gemm_mma<<<dim3(V_/128, N_/128), 256>>>(px, pow_h, pow_l, out_b, out,
                                            N_, D_, V_, 0, 0, 0, 0, 0);
    lsm_kernel<<<N_, 256>>>(out);

    if (out_size > N_*V_) {
        write_aux_kernel<<<1, 1>>>(out);
    }
}

// round 13
// speedup vs baseline: 1.6118x; 1.6118x over previous
#include <cuda_runtime.h>
#include <cuda_bf16.h>
#include <math.h>

#define S_ 512
#define B_ 8
#define D_ 512
#define H_ 8
#define HD_ 64
#define E_ 4
#define L_ 6
#define FF_ 2048
#define V_ 32000
#define N_ 4096
#define EPS_ 1e-5f
#define NEGINF_ (-3.402823466e38f)

// ---------------- scratch (static device globals; no allocation) ----------------
__device__ float g_x[N_*D_];
__device__ float g_tmp[N_*D_];
__device__ float g_q[E_*N_*D_];
__device__ float g_k[E_*N_*D_];
__device__ float g_v[E_*N_*D_];
__device__ float g_ctx[E_*N_*D_];
__device__ float g_h[N_*FF_];
__device__ float g_gate[N_*E_];
__device__ float g_aux;

// converted weights: [M][K] bf16, hi/lo split
__device__ __nv_bfloat16 g_wq_h[L_*E_*D_*D_], g_wq_l[L_*E_*D_*D_];
__device__ __nv_bfloat16 g_wk_h[L_*E_*D_*D_], g_wk_l[L_*E_*D_*D_];
__device__ __nv_bfloat16 g_wv_h[L_*E_*D_*D_], g_wv_l[L_*E_*D_*D_];
__device__ __nv_bfloat16 g_wo_h[L_*E_*D_*D_], g_wo_l[L_*E_*D_*D_];
__device__ __nv_bfloat16 g_w1_h[L_*D_*FF_],   g_w1_l[L_*D_*FF_];
__device__ __nv_bfloat16 g_w2_h[L_*FF_*D_],   g_w2_l[L_*FF_*D_];
__device__ __nv_bfloat16 g_ow_h[(size_t)D_*V_], g_ow_l[(size_t)D_*V_];

// ---------------- asm helpers ----------------
__device__ __forceinline__ void ldsm4(unsigned* r, unsigned addr)
{
    asm volatile(
        "ldmatrix.sync.aligned.m8n8.x4.shared.b16 {%0,%1,%2,%3}, [%4];"
        : "=r"(r[0]), "=r"(r[1]), "=r"(r[2]), "=r"(r[3])
        : "r"(addr));
}

__device__ __forceinline__ void mma16816(float* d, const unsigned* a, unsigned b0, unsigned b1)
{
    asm volatile(
        "mma.sync.aligned.m16n8k16.row.col.f32.bf16.bf16.f32 "
        "{%0,%1,%2,%3},{%4,%5,%6,%7},{%8,%9},{%0,%1,%2,%3};"
        : "+f"(d[0]), "+f"(d[1]), "+f"(d[2]), "+f"(d[3])
        : "r"(a[0]), "r"(a[1]), "r"(a[2]), "r"(a[3]), "r"(b0), "r"(b1));
}

// fast exp on FMA pipe: exp(x) for x in [-80, 0]. 2^(x*log2e) with
// degree-5 Taylor for the fraction and exponent-field add for the integer part.
__device__ __forceinline__ float fexp(float x)
{
    float y = x * 1.4426950408889634f;
    float n = rintf(y);
    float f = y - n;
    float p = 0.0013333558f;
    p = fmaf(p, f, 0.0096181291f);
    p = fmaf(p, f, 0.0555041087f);
    p = fmaf(p, f, 0.2402265070f);
    p = fmaf(p, f, 0.6931471806f);
    p = fmaf(p, f, 1.0f);
    return __int_as_float(__float_as_int(p) + (((int)n) << 23));
}

// ---------------- weight convert: W[K][M] fp32 -> Hi/Lo[M][K] bf16 ----------------
__global__ __launch_bounds__(256) void convert_w(
    const float* __restrict__ W, __nv_bfloat16* __restrict__ Hi,
    __nv_bfloat16* __restrict__ Lo, int K, int M, size_t inz, size_t outz)
{
    W  += (size_t)blockIdx.z * inz;
    Hi += (size_t)blockIdx.z * outz;
    Lo += (size_t)blockIdx.z * outz;
    __shared__ float tile[32][33];
    int m0 = blockIdx.x * 32, k0 = blockIdx.y * 32;
    int tx = threadIdx.x & 31, ty = threadIdx.x >> 5;
    #pragma unroll
    for (int i = 0; i < 32; i += 8)
        tile[ty + i][tx] = W[(size_t)(k0 + ty + i) * M + m0 + tx];
    __syncthreads();
    #pragma unroll
    for (int i = 0; i < 32; i += 8) {
        float v = tile[tx][ty + i];
        __nv_bfloat16 h = __float2bfloat16(v);
        float r = v - __bfloat162float(h);
        size_t o = (size_t)(m0 + ty + i) * K + k0 + tx;
        Hi[o] = h;
        Lo[o] = __float2bfloat16(r);
    }
}

// ---------------- embed + positional encoding (+ zero aux) ----------------
__global__ void embed_kernel(const int* __restrict__ src, const float* __restrict__ emb)
{
    int n = blockIdx.x;
    int s = n / B_;
    if (n == 0 && threadIdx.x == 0) g_aux = 0.f;
    int tok = src[n];
    const float scale = 22.62741699796952f;
    for (int d = threadIdx.x; d < D_; d += blockDim.x) {
        int j = d >> 1;
        float div = expf((float)(2*j) * (-9.210340371976184f / (float)D_));
        float ang = (float)s * div;
        float pe = (d & 1) ? cosf(ang) : sinf(ang);
        g_x[(size_t)n*D_ + d] = emb[(size_t)tok*D_ + d] * scale + pe;
    }
}

// ---------------- gate ----------------
__global__ void gate_kernel(const float* __restrict__ gw, const float* __restrict__ gb)
{
    int n = blockIdx.x;
    int t = threadIdx.x;
    float p0=0.f, p1=0.f, p2=0.f, p3=0.f;
    for (int d = t; d < D_; d += 128) {
        float xv = g_x[(size_t)n*D_ + d];
        const float* w = gw + (size_t)d*E_;
        p0 = fmaf(xv, w[0], p0);
        p1 = fmaf(xv, w[1], p1);
        p2 = fmaf(xv, w[2], p2);
        p3 = fmaf(xv, w[3], p3);
    }
    __shared__ float red[4][128];
    red[0][t]=p0; red[1][t]=p1; red[2][t]=p2; red[3][t]=p3;
    __syncthreads();
    for (int off = 64; off > 0; off >>= 1) {
        if (t < off) {
            red[0][t]+=red[0][t+off]; red[1][t]+=red[1][t+off];
            red[2][t]+=red[2][t+off]; red[3][t]+=red[3][t+off];
        }
        __syncthreads();
    }
    if (t == 0) {
        float l0=red[0][0]+gb[0], l1=red[1][0]+gb[1], l2=red[2][0]+gb[2], l3=red[3][0]+gb[3];
        float mx = fmaxf(fmaxf(l0,l1), fmaxf(l2,l3));
        float e0=expf(l0-mx), e1=expf(l1-mx), e2=expf(l2-mx), e3=expf(l3-mx);
        float inv = 1.f / (e0+e1+e2+e3);
        g_gate[n*4+0]=e0*inv; g_gate[n*4+1]=e1*inv; g_gate[n*4+2]=e2*inv; g_gate[n*4+3]=e3*inv;
    }
}

// ---------------- aux loss ----------------
__global__ void aux_kernel()
{
    __shared__ float red[4][256];
    int t = threadIdx.x;
    float p0=0.f, p1=0.f, p2=0.f, p3=0.f;
    for (int n = t; n < N_; n += 256) {
        p0+=g_gate[n*4+0]; p1+=g_gate[n*4+1];
        p2+=g_gate[n*4+2]; p3+=g_gate[n*4+3];
    }
    red[0][t]=p0; red[1][t]=p1; red[2][t]=p2; red[3][t]=p3;
    __syncthreads();
    for (int off = 128; off > 0; off >>= 1) {
        if (t < off) {
            red[0][t]+=red[0][t+off]; red[1][t]+=red[1][t+off];
            red[2][t]+=red[2][t+off]; red[3][t]+=red[3][t+off];
        }
        __syncthreads();
    }
    if (t == 0) {
        float i0=red[0][0], i1=red[1][0], i2=red[2][0], i3=red[3][0];
        float mean = (i0+i1+i2+i3)*0.25f;
        float d0=i0-mean, d1=i1-mean, d2=i2-mean, d3=i3-mean;
        float var = (d0*d0+d1*d1+d2*d2+d3*d3)*0.25f;
        g_aux += var / (mean*mean + 1e-10f);
    }
}

// ---------------- tensor-core GEMM (R5 config: 128x64, fp32 A, in-kernel split) ---
#define APITCH 40

__global__ __launch_bounds__(256) void gemm_mma(
    const float* __restrict__ A,
    const __nv_bfloat16* __restrict__ Wh, const __nv_bfloat16* __restrict__ Wl,
    const float* __restrict__ bias, float* __restrict__ C,
    int N, int K, int M,
    size_t az, size_t wz, size_t bz, size_t cz, int relu)
{
    A    += (size_t)blockIdx.z * az;
    Wh   += (size_t)blockIdx.z * wz;
    Wl   += (size_t)blockIdx.z * wz;
    bias += (size_t)blockIdx.z * bz;
    C    += (size_t)blockIdx.z * cz;

    __shared__ __nv_bfloat16 sAh[128*APITCH];
    __shared__ __nv_bfloat16 sAl[128*APITCH];
    __shared__ __nv_bfloat16 sBh[64*APITCH];
    __shared__ __nv_bfloat16 sBl[64*APITCH];

    const int t = threadIdx.x;
    const int lane = t & 31;
    const int wid = t >> 5;
    const int n0 = blockIdx.y * 128;
    const int m0 = blockIdx.x * 64;
    const int wm = (wid >> 1) * 32;
    const int wn = (wid & 1) * 32;

    const int lrow = lane & 15;
    const int lk = (lane >> 4) * 8;
    const unsigned aBaseH = (unsigned)__cvta_generic_to_shared(sAh) + (unsigned)(((wm + lrow)*APITCH + lk)*2);
    const unsigned aBaseL = (unsigned)__cvta_generic_to_shared(sAl) + (unsigned)(((wm + lrow)*APITCH + lk)*2);
    const unsigned bBaseH = (unsigned)__cvta_generic_to_shared(sBh) + (unsigned)(((wn + lrow)*APITCH + lk)*2);
    const unsigned bBaseL = (unsigned)__cvta_generic_to_shared(sBl) + (unsigned)(((wn + lrow)*APITCH + lk)*2);

    float acc[2][4][4];
    #pragma unroll
    for (int i = 0; i < 2; i++) {
        #pragma unroll
        for (int j = 0; j < 4; j++) {
            #pragma unroll
            for (int c = 0; c < 4; c++) {
                acc[i][j][c] = 0.f;
            }
        }
    }

    const int brow = t >> 2;
    const int bkq = (t & 3) * 8;

    for (int k0 = 0; k0 < K; k0 += 32) {
        #pragma unroll
        for (int i = 0; i < 4; i++) {
            int idx = t + i*256;
            int row = idx >> 3;
            int kq = (idx & 7) * 4;
            float4 v = *(const float4*)(A + (size_t)(n0+row)*K + k0 + kq);
            __nv_bfloat16 h0 = __float2bfloat16(v.x);
            __nv_bfloat16 h1 = __float2bfloat16(v.y);
            __nv_bfloat16 h2 = __float2bfloat16(v.z);
            __nv_bfloat16 h3 = __float2bfloat16(v.w);
            __nv_bfloat16 e0 = __float2bfloat16(v.x - __bfloat162float(h0));
            __nv_bfloat16 e1 = __float2bfloat16(v.y - __bfloat162float(h1));
            __nv_bfloat16 e2 = __float2bfloat16(v.z - __bfloat162float(h2));
            __nv_bfloat16 e3 = __float2bfloat16(v.w - __bfloat162float(h3));
            __nv_bfloat162* ph = (__nv_bfloat162*)(sAh + row*APITCH + kq);
            __nv_bfloat162* pl = (__nv_bfloat162*)(sAl + row*APITCH + kq);
            ph[0] = __halves2bfloat162(h0, h1);
            ph[1] = __halves2bfloat162(h2, h3);
            pl[0] = __halves2bfloat162(e0, e1);
            pl[1] = __halves2bfloat162(e2, e3);
        }
        {
            const __nv_bfloat16* gh = Wh + (size_t)(m0+brow)*K + k0 + bkq;
            const __nv_bfloat16* gl = Wl + (size_t)(m0+brow)*K + k0 + bkq;
            uint4 vh = *(const uint4*)gh;
            uint4 vl = *(const uint4*)gl;
            unsigned* ph = (unsigned*)(sBh + brow*APITCH + bkq);
            unsigned* pl = (unsigned*)(sBl + brow*APITCH + bkq);
            ph[0] = vh.x; ph[1] = vh.y; ph[2] = vh.z; ph[3] = vh.w;
            pl[0] = vl.x; pl[1] = vl.y; pl[2] = vl.z; pl[3] = vl.w;
        }
        __syncthreads();

        #pragma unroll
        for (int ks = 0; ks < 2; ks++) {
            unsigned ko = (unsigned)(ks * 32);
            unsigned aH[2][4];
            unsigned aL[2][4];
            unsigned bH[2][4];
            unsigned bL[2][4];
            ldsm4(aH[0], aBaseH + ko);
            ldsm4(aH[1], aBaseH + 1280u + ko);
            ldsm4(aL[0], aBaseL + ko);
            ldsm4(aL[1], aBaseL + 1280u + ko);
            ldsm4(bH[0], bBaseH + ko);
            ldsm4(bH[1], bBaseH + 1280u + ko);
            ldsm4(bL[0], bBaseL + ko);
            ldsm4(bL[1], bBaseL + 1280u + ko);
            #pragma unroll
            for (int mt = 0; mt < 2; mt++) {
                #pragma unroll
                for (int np = 0; np < 2; np++) {
                    #pragma unroll
                    for (int sub = 0; sub < 2; sub++) {
                        float* d = acc[mt][np*2 + sub];
                        mma16816(d, aH[mt], bH[np][sub], bH[np][sub+2]);
                        mma16816(d, aH[mt], bL[np][sub], bL[np][sub+2]);
                        mma16816(d, aL[mt], bH[np][sub], bH[np][sub+2]);
                    }
                }
            }
        }
        __syncthreads();
    }

    const int gr = lane >> 2;
    const int q = lane & 3;
    #pragma unroll
    for (int mt = 0; mt < 2; mt++) {
        int row = n0 + wm + mt*16 + gr;
        #pragma unroll
        for (int nt = 0; nt < 4; nt++) {
            int col = m0 + wn + nt*8 + q*2;
            float bx = bias[col];
            float by = bias[col+1];
            float c0 = acc[mt][nt][0] + bx;
            float c1 = acc[mt][nt][1] + by;
            float c2 = acc[mt][nt][2] + bx;
            float c3 = acc[mt][nt][3] + by;
            if (relu) {
                c0 = fmaxf(c0, 0.f); c1 = fmaxf(c1, 0.f);
                c2 = fmaxf(c2, 0.f); c3 = fmaxf(c3, 0.f);
            }
            *(float2*)(C + (size_t)row*M + col)     = make_float2(c0, c1);
            *(float2*)(C + (size_t)(row+8)*M + col) = make_float2(c2, c3);
        }
    }
}

// ---------------- causal attention per (b,e,h): chunked online softmax ------------
__global__ __launch_bounds__(128) void attn_kernel()
{
    int qc  = blockIdx.x;
    int beh = blockIdx.y;
    int h = beh & 7;
    int e = (beh >> 3) & 3;
    int b = beh >> 5;
    int t = threadIdx.x;
    int s = qc*128 + t;

    __shared__ float4 Ks[64][16];
    __shared__ float4 Vs[64][16];

    size_t base = (size_t)e*N_*D_ + (size_t)h*HD_;
    const float* qp = g_q + base + (size_t)(s*B_+b)*D_;

    float4 q4[16];
    #pragma unroll
    for (int i = 0; i < 16; i++) q4[i] = *(const float4*)(qp + i*4);

    float4 a4[16];
    #pragma unroll
    for (int i = 0; i < 16; i++) a4[i] = make_float4(0.f, 0.f, 0.f, 0.f);
    float m = NEGINF_, lsum = 0.f;

    int nkc = 2*qc + 2;
    for (int kc = 0; kc < nkc; kc++) {
        int j0 = kc * 64;
        __syncthreads();
        #pragma unroll
        for (int i = 0; i < 8; i++) {
            int idx = t + i*128;
            int j = idx >> 4;
            int cc = idx & 15;
            size_t off = base + (size_t)((j0+j)*B_ + b)*D_ + cc*4;
            Ks[j][cc] = *(const float4*)(g_k + off);
            Vs[j][cc] = *(const float4*)(g_v + off);
        }
        __syncthreads();
        for (int sub = 0; sub < 4; sub++) {
            int j0s = j0 + sub*16;
            if (j0s > s) break;
            float sc[16];
            #pragma unroll
            for (int jj = 0; jj < 16; jj++) {
                int j = sub*16 + jj;
                float s0=0.f, s1=0.f, s2=0.f, s3=0.f;
                #pragma unroll
                for (int i = 0; i < 16; i++) {
                    float4 kk = Ks[j][i];
                    s0 = fmaf(q4[i].x, kk.x, s0);
                    s1 = fmaf(q4[i].y, kk.y, s1);
                    s2 = fmaf(q4[i].z, kk.z, s2);
                    s3 = fmaf(q4[i].w, kk.w, s3);
                }
                float v = ((s0+s1)+(s2+s3)) * 0.125f;
                sc[jj] = (j0s + jj <= s) ? v : NEGINF_;
            }
            float cm = sc[0];
            #pragma unroll
            for (int jj = 1; jj < 16; jj++) cm = fmaxf(cm, sc[jj]);
            float newm = fmaxf(m, cm);
            float alpha = __expf(m - newm);
            lsum *= alpha;
            #pragma unroll
            for (int i = 0; i < 16; i++) {
                a4[i].x *= alpha; a4[i].y *= alpha;
                a4[i].z *= alpha; a4[i].w *= alpha;
            }
            m = newm;
            #pragma unroll
            for (int jj = 0; jj < 16; jj++) {
                float p = __expf(sc[jj] - m);
                lsum += p;
                int j = sub*16 + jj;
                #pragma unroll
                for (int i = 0; i < 16; i++) {
                    float4 vv = Vs[j][i];
                    a4[i].x = fmaf(p, vv.x, a4[i].x);
                    a4[i].y = fmaf(p, vv.y, a4[i].y);
                    a4[i].z = fmaf(p, vv.z, a4[i].z);
                    a4[i].w = fmaf(p, vv.w, a4[i].w);
                }
            }
        }
    }
    float inv = 1.f / lsum;
    float* op = g_ctx + base + (size_t)(s*B_+b)*D_;
    #pragma unroll
    for (int i = 0; i < 16; i++) {
        float4 o = make_float4(a4[i].x*inv, a4[i].y*inv, a4[i].z*inv, a4[i].w*inv);
        *(float4*)(op + i*4) = o;
    }
}

// ---------------- block sum helper ----------------
__device__ __forceinline__ float blocksum128(float v)
{
    __shared__ float sh[4];
    #pragma unroll
    for (int o = 16; o > 0; o >>= 1) v += __shfl_down_sync(0xffffffffu, v, o);
    __syncthreads();
    if ((threadIdx.x & 31) == 0) sh[threadIdx.x >> 5] = v;
    __syncthreads();
    return sh[0] + sh[1] + sh[2] + sh[3];
}

// ---------------- fused: x = LN2(LN1(x + sum_e gate*eo)) ----------------
__global__ void comb_ln12_kernel(const float* __restrict__ g1, const float* __restrict__ b1v,
                                 const float* __restrict__ g2, const float* __restrict__ b2v)
{
    int n = blockIdx.x;
    int t = threadIdx.x;           // 128 threads, one float4 each
    int idx = n*128 + t;
    const float4* eo = (const float4*)g_q;
    const int z = N_*D_/4;
    float ga0 = g_gate[n*4+0];
    float ga1 = g_gate[n*4+1];
    float ga2 = g_gate[n*4+2];
    float ga3 = g_gate[n*4+3];
    float4 v0 = eo[idx];
    float4 v1 = eo[z+idx];
    float4 v2 = eo[2*z+idx];
    float4 v3 = eo[3*z+idx];
    float4 xr = ((const float4*)g_x)[idx];
    float c0 = xr.x + ga0*v0.x + ga1*v1.x + ga2*v2.x + ga3*v3.x;
    float c1 = xr.y + ga0*v0.y + ga1*v1.y + ga2*v2.y + ga3*v3.y;
    float c2 = xr.z + ga0*v0.z + ga1*v1.z + ga2*v2.z + ga3*v3.z;
    float c3 = xr.w + ga0*v0.w + ga1*v1.w + ga2*v2.w + ga3*v3.w;

    // LN1
    float mean = blocksum128(c0+c1+c2+c3) * (1.f/D_);
    float d0 = c0-mean, d1 = c1-mean, d2 = c2-mean, d3 = c3-mean;
    float var = blocksum128(d0*d0 + d1*d1 + d2*d2 + d3*d3) * (1.f/D_);
    float rstd = rsqrtf(var + EPS_);
    float4 gg1 = ((const float4*)g1)[t];
    float4 bb1 = ((const float4*)b1v)[t];
    float y0 = d0*rstd*gg1.x + bb1.x;
    float y1 = d1*rstd*gg1.y + bb1.y;
    float y2 = d2*rstd*gg1.z + bb1.z;
    float y3 = d3*rstd*gg1.w + bb1.w;

    // LN2
    float mean2 = blocksum128(y0+y1+y2+y3) * (1.f/D_);
    float e0 = y0-mean2, e1 = y1-mean2, e2 = y2-mean2, e3 = y3-mean2;
    float var2 = blocksum128(e0*e0 + e1*e1 + e2*e2 + e3*e3) * (1.f/D_);
    float rstd2 = rsqrtf(var2 + EPS_);
    float4 gg2 = ((const float4*)g2)[t];
    float4 bb2 = ((const float4*)b2v)[t];
    float4 o;
    o.x = e0*rstd2*gg2.x + bb2.x;
    o.y = e1*rstd2*gg2.y + bb2.y;
    o.z = e2*rstd2*gg2.z + bb2.z;
    o.w = e3*rstd2*gg2.w + bb2.w;
    ((float4*)g_x)[idx] = o;
}

// ---------------- LayerNorm (residual add) ----------------
__global__ void ln_kernel(const float* __restrict__ xin, const float* __restrict__ res,
                          const float* __restrict__ g, const float* __restrict__ bb,
                          float* __restrict__ out)
{
    int n = blockIdx.x;
    int t = threadIdx.x;
    float4 v = ((const float4*)(xin + (size_t)n*D_))[t];
    if (res) {
        float4 r = ((const float4*)(res + (size_t)n*D_))[t];
        v.x += r.x; v.y += r.y; v.z += r.z; v.w += r.w;
    }
    float mean = blocksum128(v.x+v.y+v.z+v.w) * (1.f/D_);
    float d0 = v.x-mean, d1 = v.y-mean, d2 = v.z-mean, d3 = v.w-mean;
    float var = blocksum128(d0*d0 + d1*d1 + d2*d2 + d3*d3) * (1.f/D_);
    float rstd = rsqrtf(var + EPS_);
    float4 gg = ((const float4*)g)[t];
    float4 bv = ((const float4*)bb)[t];
    float4 o;
    o.x = d0*rstd*gg.x + bv.x;
    o.y = d1*rstd*gg.y + bv.y;
    o.z = d2*rstd*gg.z + bv.z;
    o.w = d3*rstd*gg.w + bv.w;
    ((float4*)(out + (size_t)n*D_))[t] = o;
}

// ---------------- in-place log_softmax over V per row (FMA-pipe exp) --------------
__global__ void lsm_kernel(float* __restrict__ out)
{
    __shared__ float sh[8];
    int n = blockIdx.x;
    int t = threadIdx.x;           // 256 threads
    float4* row4 = (float4*)(out + (size_t)n*V_);
    const int NV4 = V_/4;          // 8000

    float mx = NEGINF_;
    for (int i = t; i < NV4; i += 256) {
        float4 v = row4[i];
        mx = fmaxf(mx, fmaxf(fmaxf(v.x, v.y), fmaxf(v.z, v.w)));
    }
    #pragma unroll
    for (int o = 16; o > 0; o >>= 1) mx = fmaxf(mx, __shfl_xor_sync(0xffffffffu, mx, o));
    if ((t & 31) == 0) sh[t >> 5] = mx;
    __syncthreads();
    mx = fmaxf(fmaxf(fmaxf(sh[0],sh[1]), fmaxf(sh[2],sh[3])),
               fmaxf(fmaxf(sh[4],sh[5]), fmaxf(sh[6],sh[7])));

    float sum = 0.f;
    for (int i = t; i < NV4; i += 256) {
        float4 v = row4[i];
        sum += fexp(v.x - mx) + fexp(v.y - mx) + fexp(v.z - mx) + fexp(v.w - mx);
    }
    #pragma unroll
    for (int o = 16; o > 0; o >>= 1) sum += __shfl_xor_sync(0xffffffffu, sum, o);
    __syncthreads();
    if ((t & 31) == 0) sh[t >> 5] = sum;
    __syncthreads();
    sum = ((sh[0]+sh[1]) + (sh[2]+sh[3])) + ((sh[4]+sh[5]) + (sh[6]+sh[7]));
    float lse = mx + logf(sum);

    for (int i = t; i < NV4; i += 256) {
        float4 v = row4[i];
        v.x -= lse; v.y -= lse; v.z -= lse; v.w -= lse;
        row4[i] = v;
    }
}

__global__ void write_aux_kernel(float* __restrict__ out)
{
    out[(size_t)N_*V_] = g_aux;
}

// ---------------- host orchestration ----------------
extern "C" void kernel_launch(void* const* d_in, const int* in_sizes, int n_in,
                              void* d_out, int out_size)
{
    (void)in_sizes; (void)n_in;
    const int*   src    = (const int*)  d_in[1];
    const float* emb    = (const float*)d_in[2];
    const float* gate_w = (const float*)d_in[3];
    const float* gate_b = (const float*)d_in[4];
    const float* wq     = (const float*)d_in[5];
    const float* wk     = (const float*)d_in[6];
    const float* wv     = (const float*)d_in[7];
    const float* wo     = (const float*)d_in[8];
    const float* bq     = (const float*)d_in[9];
    const float* bk     = (const float*)d_in[10];
    const float* bv     = (const float*)d_in[11];
    const float* bo     = (const float*)d_in[12];
    const float* w1     = (const float*)d_in[13];
    const float* b1     = (const float*)d_in[14];
    const float* w2     = (const float*)d_in[15];
    const float* b2     = (const float*)d_in[16];
    const float* ln1_g  = (const float*)d_in[17];
    const float* ln1_b  = (const float*)d_in[18];
    const float* ln2_g  = (const float*)d_in[19];
    const float* ln2_b  = (const float*)d_in[20];
    const float* ln3_g  = (const float*)d_in[21];
    const float* ln3_b  = (const float*)d_in[22];
    const float* lnf_g  = (const float*)d_in[23];
    const float* lnf_b  = (const float*)d_in[24];
    const float* out_w  = (const float*)d_in[25];
    const float* out_b  = (const float*)d_in[26];
    float* out = (float*)d_out;

    float *px, *ptmp, *pq, *pk, *pv, *pctx, *ph;
    cudaGetSymbolAddress((void**)&px,   g_x);
    cudaGetSymbolAddress((void**)&ptmp, g_tmp);
    cudaGetSymbolAddress((void**)&pq,   g_q);
    cudaGetSymbolAddress((void**)&pk,   g_k);
    cudaGetSymbolAddress((void**)&pv,   g_v);
    cudaGetSymbolAddress((void**)&pctx, g_ctx);
    cudaGetSymbolAddress((void**)&ph,   g_h);

    __nv_bfloat16 *pwq_h, *pwq_l, *pwk_h, *pwk_l, *pwv_h, *pwv_l, *pwo_h, *pwo_l;
    __nv_bfloat16 *pw1_h, *pw1_l, *pw2_h, *pw2_l, *pow_h, *pow_l;
    cudaGetSymbolAddress((void**)&pwq_h, g_wq_h);
    cudaGetSymbolAddress((void**)&pwq_l, g_wq_l);
    cudaGetSymbolAddress((void**)&pwk_h, g_wk_h);
    cudaGetSymbolAddress((void**)&pwk_l, g_wk_l);
    cudaGetSymbolAddress((void**)&pwv_h, g_wv_h);
    cudaGetSymbolAddress((void**)&pwv_l, g_wv_l);
    cudaGetSymbolAddress((void**)&pwo_h, g_wo_h);
    cudaGetSymbolAddress((void**)&pwo_l, g_wo_l);
    cudaGetSymbolAddress((void**)&pw1_h, g_w1_h);
    cudaGetSymbolAddress((void**)&pw1_l, g_w1_l);
    cudaGetSymbolAddress((void**)&pw2_h, g_w2_h);
    cudaGetSymbolAddress((void**)&pw2_l, g_w2_l);
    cudaGetSymbolAddress((void**)&pow_h, g_ow_h);
    cudaGetSymbolAddress((void**)&pow_l, g_ow_l);

    size_t dd = (size_t)D_*D_;
    size_t nd = (size_t)N_*D_;

    convert_w<<<dim3(D_/32, D_/32, L_*E_), 256>>>(wq, pwq_h, pwq_l, D_, D_, dd, dd);
    convert_w<<<dim3(D_/32, D_/32, L_*E_), 256>>>(wk, pwk_h, pwk_l, D_, D_, dd, dd);
    convert_w<<<dim3(D_/32, D_/32, L_*E_), 256>>>(wv, pwv_h, pwv_l, D_, D_, dd, dd);
    convert_w<<<dim3(D_/32, D_/32, L_*E_), 256>>>(wo, pwo_h, pwo_l, D_, D_, dd, dd);
    convert_w<<<dim3(FF_/32, D_/32, L_), 256>>>(w1, pw1_h, pw1_l, D_, FF_, (size_t)D_*FF_, (size_t)D_*FF_);
    convert_w<<<dim3(D_/32, FF_/32, L_), 256>>>(w2, pw2_h, pw2_l, FF_, D_, (size_t)FF_*D_, (size_t)FF_*D_);
    convert_w<<<dim3(V_/32, D_/32, 1), 256>>>(out_w, pow_h, pow_l, D_, V_, 0, 0);

    embed_kernel<<<N_, 128>>>(src, emb);

    for (int l = 0; l < L_; l++) {
        gate_kernel<<<N_, 128>>>(gate_w + (size_t)l*D_*E_, gate_b + (size_t)l*E_);
        aux_kernel<<<1, 256>>>();

        dim3 gqkv(D_/64, N_/128, E_);
        size_t woff = (size_t)l*E_*dd;
        size_t boff = (size_t)l*E_*D_;
        gemm_mma<<<gqkv, 256>>>(px, pwq_h + woff, pwq_l + woff, bq + boff, pq,
                                N_, D_, D_, 0, dd, D_, nd, 0);
        gemm_mma<<<gqkv, 256>>>(px, pwk_h + woff, pwk_l + woff, bk + boff, pk,
                                N_, D_, D_, 0, dd, D_, nd, 0);
        gemm_mma<<<gqkv, 256>>>(px, pwv_h + woff, pwv_l + woff, bv + boff, pv,
                                N_, D_, D_, 0, dd, D_, nd, 0);

        attn_kernel<<<dim3(4, B_*E_*H_), 128>>>();

        gemm_mma<<<gqkv, 256>>>(pctx, pwo_h + woff, pwo_l + woff, bo + boff, pq,
                                N_, D_, D_, nd, dd, D_, nd, 0);

        comb_ln12_kernel<<<N_, 128>>>(ln1_g + (size_t)l*D_, ln1_b + (size_t)l*D_,
                                      ln2_g + (size_t)l*D_, ln2_b + (size_t)l*D_);

        gemm_mma<<<dim3(FF_/64, N_/128), 256>>>(px, pw1_h + (size_t)l*D_*FF_, pw1_l + (size_t)l*D_*FF_,
                                                b1 + (size_t)l*FF_, ph, N_, D_, FF_, 0, 0, 0, 0, 1);
        gemm_mma<<<dim3(D_/64, N_/128), 256>>>(ph, pw2_h + (size_t)l*FF_*D_, pw2_l + (size_t)l*FF_*D_,
                                               b2 + (size_t)l*D_, ptmp, N_, FF_, D_, 0, 0, 0, 0, 0);

        ln_kernel<<<N_, 128>>>(px, ptmp, ln3_g + (size_t)l*D_, ln3_b + (size_t)l*D_, px);
    }

    ln_kernel<<<N_, 128>>>(px, (const float*)0, lnf_g, lnf_b, px);

    gemm_mma<<<dim3(V_/64, N_/128), 256>>>(px, pow_h, pow_l, out_b, out,
                                           N_, D_, V_, 0, 0, 0, 0, 0);
    lsm_kernel<<<N_, 256>>>(out);

    if (out_size > N_*V_) {
        write_aux_kernel<<<1, 1>>>(out);
    }
}

// round 17
// speedup vs baseline: 1.6505x; 1.0240x over previous
#include <cuda_runtime.h>
#include <cuda_bf16.h>
#include <math.h>

#define S_ 512
#define B_ 8
#define D_ 512
#define H_ 8
#define HD_ 64
#define E_ 4
#define L_ 6
#define FF_ 2048
#define V_ 32000
#define N_ 4096
#define QKVM_ (E_*3*D_)      // 6144
#define EPS_ 1e-5f
#define NEGINF_ (-3.402823466e38f)

// ---------------- scratch (static device globals; no allocation) ----------------
__device__ float g_x[N_*D_];
__device__ float g_tmp[N_*D_];
__device__ float g_qkv[(size_t)N_*QKVM_];   // packed QKV output [n][e*3D + part*D + d]
__device__ float g_q[E_*N_*D_];             // eo (WO output)
__device__ float g_ctx[E_*N_*D_];
__device__ float g_h[N_*FF_];
__device__ float g_gate[N_*E_];
__device__ float g_bqkv[L_*QKVM_];          // packed QKV bias
__device__ float g_aux;

// converted weights: [M][K] bf16, hi/lo split
__device__ __nv_bfloat16 g_wqkv_h[L_*E_*3*D_*D_], g_wqkv_l[L_*E_*3*D_*D_];
__device__ __nv_bfloat16 g_wo_h[L_*E_*D_*D_],     g_wo_l[L_*E_*D_*D_];
__device__ __nv_bfloat16 g_w1_h[L_*D_*FF_],       g_w1_l[L_*D_*FF_];
__device__ __nv_bfloat16 g_w2_h[L_*FF_*D_],       g_w2_l[L_*FF_*D_];
__device__ __nv_bfloat16 g_ow_h[(size_t)D_*V_],   g_ow_l[(size_t)D_*V_];

// ---------------- asm helpers ----------------
__device__ __forceinline__ void ldsm4(unsigned* r, unsigned addr)
{
    asm volatile(
        "ldmatrix.sync.aligned.m8n8.x4.shared.b16 {%0,%1,%2,%3}, [%4];"
        : "=r"(r[0]), "=r"(r[1]), "=r"(r[2]), "=r"(r[3])
        : "r"(addr));
}

__device__ __forceinline__ void mma16816(float* d, const unsigned* a, unsigned b0, unsigned b1)
{
    asm volatile(
        "mma.sync.aligned.m16n8k16.row.col.f32.bf16.bf16.f32 "
        "{%0,%1,%2,%3},{%4,%5,%6,%7},{%8,%9},{%0,%1,%2,%3};"
        : "+f"(d[0]), "+f"(d[1]), "+f"(d[2]), "+f"(d[3])
        : "r"(a[0]), "r"(a[1]), "r"(a[2]), "r"(a[3]), "r"(b0), "r"(b1));
}

// fast exp on FMA pipe
__device__ __forceinline__ float fexp(float x)
{
    float y = x * 1.4426950408889634f;
    float n = rintf(y);
    float f = y - n;
    float p = 0.0013333558f;
    p = fmaf(p, f, 0.0096181291f);
    p = fmaf(p, f, 0.0555041087f);
    p = fmaf(p, f, 0.2402265070f);
    p = fmaf(p, f, 0.6931471806f);
    p = fmaf(p, f, 1.0f);
    return __int_as_float(__float_as_int(p) + (((int)n) << 23));
}

// ---------------- weight convert: W[K][M] fp32 -> Hi/Lo[M][K] bf16 ----------------
__global__ __launch_bounds__(256) void convert_w(
    const float* __restrict__ W, __nv_bfloat16* __restrict__ Hi,
    __nv_bfloat16* __restrict__ Lo, int K, int M, size_t inz, size_t outz)
{
    W  += (size_t)blockIdx.z * inz;
    Hi += (size_t)blockIdx.z * outz;
    Lo += (size_t)blockIdx.z * outz;
    __shared__ float tile[32][33];
    int m0 = blockIdx.x * 32, k0 = blockIdx.y * 32;
    int tx = threadIdx.x & 31, ty = threadIdx.x >> 5;
    #pragma unroll
    for (int i = 0; i < 32; i += 8)
        tile[ty + i][tx] = W[(size_t)(k0 + ty + i) * M + m0 + tx];
    __syncthreads();
    #pragma unroll
    for (int i = 0; i < 32; i += 8) {
        float v = tile[tx][ty + i];
        __nv_bfloat16 h = __float2bfloat16(v);
        float r = v - __bfloat162float(h);
        size_t o = (size_t)(m0 + ty + i) * K + k0 + tx;
        Hi[o] = h;
        Lo[o] = __float2bfloat16(r);
    }
}

// ---------------- pack QKV bias: [L][E*3D] <- bq/bk/bv [L][E][D] ----------------
__global__ void pack_bias(const float* __restrict__ bq, const float* __restrict__ bk,
                          const float* __restrict__ bv)
{
    int i = blockIdx.x*256 + threadIdx.x;      // over L*E*3*D
    int d = i & (D_-1);
    int r = i >> 9;                            // l*E*3 + e*3 + part
    int part = r % 3;
    int e = (r/3) % E_;
    int l = r/(3*E_);
    const float* src = (part == 0) ? bq : ((part == 1) ? bk : bv);
    g_bqkv[i] = src[(size_t)(l*E_+e)*D_ + d];
}

// ---------------- embed + positional encoding (+ zero aux) ----------------
__global__ void embed_kernel(const int* __restrict__ src, const float* __restrict__ emb)
{
    int n = blockIdx.x;
    int s = n / B_;
    if (n == 0 && threadIdx.x == 0) g_aux = 0.f;
    int tok = src[n];
    const float scale = 22.62741699796952f;
    for (int d = threadIdx.x; d < D_; d += blockDim.x) {
        int j = d >> 1;
        float div = expf((float)(2*j) * (-9.210340371976184f / (float)D_));
        float ang = (float)s * div;
        float pe = (d & 1) ? cosf(ang) : sinf(ang);
        g_x[(size_t)n*D_ + d] = emb[(size_t)tok*D_ + d] * scale + pe;
    }
}

// ---------------- gate ----------------
__global__ void gate_kernel(const float* __restrict__ gw, const float* __restrict__ gb)
{
    int n = blockIdx.x;
    int t = threadIdx.x;
    float p0=0.f, p1=0.f, p2=0.f, p3=0.f;
    for (int d = t; d < D_; d += 128) {
        float xv = g_x[(size_t)n*D_ + d];
        const float* w = gw + (size_t)d*E_;
        p0 = fmaf(xv, w[0], p0);
        p1 = fmaf(xv, w[1], p1);
        p2 = fmaf(xv, w[2], p2);
        p3 = fmaf(xv, w[3], p3);
    }
    __shared__ float red[4][128];
    red[0][t]=p0; red[1][t]=p1; red[2][t]=p2; red[3][t]=p3;
    __syncthreads();
    for (int off = 64; off > 0; off >>= 1) {
        if (t < off) {
            red[0][t]+=red[0][t+off]; red[1][t]+=red[1][t+off];
            red[2][t]+=red[2][t+off]; red[3][t]+=red[3][t+off];
        }
        __syncthreads();
    }
    if (t == 0) {
        float l0=red[0][0]+gb[0], l1=red[1][0]+gb[1], l2=red[2][0]+gb[2], l3=red[3][0]+gb[3];
        float mx = fmaxf(fmaxf(l0,l1), fmaxf(l2,l3));
        float e0=expf(l0-mx), e1=expf(l1-mx), e2=expf(l2-mx), e3=expf(l3-mx);
        float inv = 1.f / (e0+e1+e2+e3);
        g_gate[n*4+0]=e0*inv; g_gate[n*4+1]=e1*inv; g_gate[n*4+2]=e2*inv; g_gate[n*4+3]=e3*inv;
    }
}

// ---------------- aux loss ----------------
__global__ void aux_kernel()
{
    __shared__ float red[4][256];
    int t = threadIdx.x;
    float p0=0.f, p1=0.f, p2=0.f, p3=0.f;
    for (int n = t; n < N_; n += 256) {
        p0+=g_gate[n*4+0]; p1+=g_gate[n*4+1];
        p2+=g_gate[n*4+2]; p3+=g_gate[n*4+3];
    }
    red[0][t]=p0; red[1][t]=p1; red[2][t]=p2; red[3][t]=p3;
    __syncthreads();
    for (int off = 128; off > 0; off >>= 1) {
        if (t < off) {
            red[0][t]+=red[0][t+off]; red[1][t]+=red[1][t+off];
            red[2][t]+=red[2][t+off]; red[3][t]+=red[3][t+off];
        }
        __syncthreads();
    }
    if (t == 0) {
        float i0=red[0][0], i1=red[1][0], i2=red[2][0], i3=red[3][0];
        float mean = (i0+i1+i2+i3)*0.25f;
        float d0=i0-mean, d1=i1-mean, d2=i2-mean, d3=i3-mean;
        float var = (d0*d0+d1*d1+d2*d2+d3*d3)*0.25f;
        g_aux += var / (mean*mean + 1e-10f);
    }
}

// ---------------- tensor-core GEMM: double-buffered, 128x64 tile ------------------
// C = A(fp32 [N][K]) @ W(split-bf16 [M][K]) + bias. 256 threads.
// Two smem stages; next chunk's LDGs issued before the MMA phase (latency hidden),
// converted+stored after MMAs; ONE barrier per chunk.
#define APITCH 40
#define STG_AH 0
#define STG_AL 10240
#define STG_BH 20480
#define STG_BL 25600
#define STAGE_SZ 30720
#define GSMEM (2*STAGE_SZ)

__global__ __launch_bounds__(256) void gemm_mma(
    const float* __restrict__ A,
    const __nv_bfloat16* __restrict__ Wh, const __nv_bfloat16* __restrict__ Wl,
    const float* __restrict__ bias, float* __restrict__ C,
    int N, int K, int M,
    size_t az, size_t wz, size_t bz, size_t cz, int relu)
{
    extern __shared__ char smem[];
    A    += (size_t)blockIdx.z * az;
    Wh   += (size_t)blockIdx.z * wz;
    Wl   += (size_t)blockIdx.z * wz;
    bias += (size_t)blockIdx.z * bz;
    C    += (size_t)blockIdx.z * cz;

    const unsigned sb = (unsigned)__cvta_generic_to_shared(smem);
    const int t = threadIdx.x;
    const int lane = t & 31;
    const int wid = t >> 5;
    const int n0 = blockIdx.y * 128;
    const int m0 = blockIdx.x * 64;
    const int wm = (wid >> 1) * 32;
    const int wn = (wid & 1) * 32;

    const int lrow = lane & 15;
    const int lk = (lane >> 4) * 8;
    const unsigned aoff = (unsigned)(((wm + lrow)*APITCH + lk)*2);
    const unsigned boff = (unsigned)(((wn + lrow)*APITCH + lk)*2);

    float acc[2][4][4];
    #pragma unroll
    for (int i = 0; i < 2; i++) {
        #pragma unroll
        for (int j = 0; j < 4; j++) {
            #pragma unroll
            for (int c = 0; c < 4; c++) {
                acc[i][j][c] = 0.f;
            }
        }
    }

    const int arow0 = t >> 3;             // A: idx=t+i*256 -> row=idx>>3, kq=(idx&7)*4
    const int brow = t >> 2;
    const int bkq = (t & 3) * 8;

    // ---- chunk 0: load + convert into stage 0 ----
    {
        char* st = smem;
        #pragma unroll
        for (int i = 0; i < 4; i++) {
            int idx = t + i*256;
            int row = idx >> 3;
            int kq = (idx & 7) * 4;
            float4 v = *(const float4*)(A + (size_t)(n0+row)*K + kq);
            __nv_bfloat16 h0 = __float2bfloat16(v.x);
            __nv_bfloat16 h1 = __float2bfloat16(v.y);
            __nv_bfloat16 h2 = __float2bfloat16(v.z);
            __nv_bfloat16 h3 = __float2bfloat16(v.w);
            __nv_bfloat16 e0 = __float2bfloat16(v.x - __bfloat162float(h0));
            __nv_bfloat16 e1 = __float2bfloat16(v.y - __bfloat162float(h1));
            __nv_bfloat16 e2 = __float2bfloat16(v.z - __bfloat162float(h2));
            __nv_bfloat16 e3 = __float2bfloat16(v.w - __bfloat162float(h3));
            __nv_bfloat162* ph = (__nv_bfloat162*)(st + STG_AH + (row*APITCH + kq)*2);
            __nv_bfloat162* pl = (__nv_bfloat162*)(st + STG_AL + (row*APITCH + kq)*2);
            ph[0] = __halves2bfloat162(h0, h1);
            ph[1] = __halves2bfloat162(h2, h3);
            pl[0] = __halves2bfloat162(e0, e1);
            pl[1] = __halves2bfloat162(e2, e3);
        }
        uint4 vh = *(const uint4*)(Wh + (size_t)(m0+brow)*K + bkq);
        uint4 vl = *(const uint4*)(Wl + (size_t)(m0+brow)*K + bkq);
        *(uint4*)(st + STG_BH + (brow*APITCH + bkq)*2) = vh;
        *(uint4*)(st + STG_BL + (brow*APITCH + bkq)*2) = vl;
    }
    __syncthreads();

    const int nk = K >> 5;
    for (int kc = 0; kc < nk; kc++) {
        const int cur = kc & 1;
        const bool has = (kc + 1) < nk;
        float4 pa[4];
        uint4 pbh, pbl;
        if (has) {
            const int k1 = (kc + 1) * 32;
            #pragma unroll
            for (int i = 0; i < 4; i++) {
                int idx = t + i*256;
                int row = idx >> 3;
                int kq = (idx & 7) * 4;
                pa[i] = *(const float4*)(A + (size_t)(n0+row)*K + k1 + kq);
            }
            pbh = *(const uint4*)(Wh + (size_t)(m0+brow)*K + k1 + bkq);
            pbl = *(const uint4*)(Wl + (size_t)(m0+brow)*K + k1 + bkq);
        }

        // ---- MMA phase on stage cur ----
        const unsigned sg = sb + (unsigned)(cur*STAGE_SZ);
        const unsigned aBaseH = sg + STG_AH + aoff;
        const unsigned aBaseL = sg + STG_AL + aoff;
        const unsigned bBaseH = sg + STG_BH + boff;
        const unsigned bBaseL = sg + STG_BL + boff;
        #pragma unroll
        for (int ks = 0; ks < 2; ks++) {
            unsigned ko = (unsigned)(ks * 32);
            unsigned aH[2][4];
            unsigned aL[2][4];
            unsigned bH[2][4];
            unsigned bL[2][4];
            ldsm4(aH[0], aBaseH + ko);
            ldsm4(aH[1], aBaseH + 1280u + ko);
            ldsm4(aL[0], aBaseL + ko);
            ldsm4(aL[1], aBaseL + 1280u + ko);
            ldsm4(bH[0], bBaseH + ko);
            ldsm4(bH[1], bBaseH + 1280u + ko);
            ldsm4(bL[0], bBaseL + ko);
            ldsm4(bL[1], bBaseL + 1280u + ko);
            #pragma unroll
            for (int mt = 0; mt < 2; mt++) {
                #pragma unroll
                for (int np = 0; np < 2; np++) {
                    #pragma unroll
                    for (int sub = 0; sub < 2; sub++) {
                        float* d = acc[mt][np*2 + sub];
                        mma16816(d, aH[mt], bH[np][sub], bH[np][sub+2]);
                        mma16816(d, aH[mt], bL[np][sub], bL[np][sub+2]);
                        mma16816(d, aL[mt], bH[np][sub], bH[np][sub+2]);
                    }
                }
            }
        }

        // ---- convert + store next chunk into stage cur^1 ----
        if (has) {
            char* st = smem + (cur^1)*STAGE_SZ;
            #pragma unroll
            for (int i = 0; i < 4; i++) {
                int idx = t + i*256;
                int row = idx >> 3;
                int kq = (idx & 7) * 4;
                float4 v = pa[i];
                __nv_bfloat16 h0 = __float2bfloat16(v.x);
                __nv_bfloat16 h1 = __float2bfloat16(v.y);
                __nv_bfloat16 h2 = __float2bfloat16(v.z);
                __nv_bfloat16 h3 = __float2bfloat16(v.w);
                __nv_bfloat16 e0 = __float2bfloat16(v.x - __bfloat162float(h0));
                __nv_bfloat16 e1 = __float2bfloat16(v.y - __bfloat162float(h1));
                __nv_bfloat16 e2 = __float2bfloat16(v.z - __bfloat162float(h2));
                __nv_bfloat16 e3 = __float2bfloat16(v.w - __bfloat162float(h3));
                __nv_bfloat162* ph = (__nv_bfloat162*)(st + STG_AH + (row*APITCH + kq)*2);
                __nv_bfloat162* pl = (__nv_bfloat162*)(st + STG_AL + (row*APITCH + kq)*2);
                ph[0] = __halves2bfloat162(h0, h1);
                ph[1] = __halves2bfloat162(h2, h3);
                pl[0] = __halves2bfloat162(e0, e1);
                pl[1] = __halves2bfloat162(e2, e3);
            }
            *(uint4*)(st + STG_BH + (brow*APITCH + bkq)*2) = pbh;
            *(uint4*)(st + STG_BL + (brow*APITCH + bkq)*2) = pbl;
        }
        __syncthreads();
    }
    (void)arow0;

    const int gr = lane >> 2;
    const int q = lane & 3;
    #pragma unroll
    for (int mt = 0; mt < 2; mt++) {
        int row = n0 + wm + mt*16 + gr;
        #pragma unroll
        for (int nt = 0; nt < 4; nt++) {
            int col = m0 + wn + nt*8 + q*2;
            float bx = bias[col];
            float by = bias[col+1];
            float c0 = acc[mt][nt][0] + bx;
            float c1 = acc[mt][nt][1] + by;
            float c2 = acc[mt][nt][2] + bx;
            float c3 = acc[mt][nt][3] + by;
            if (relu) {
                c0 = fmaxf(c0, 0.f); c1 = fmaxf(c1, 0.f);
                c2 = fmaxf(c2, 0.f); c3 = fmaxf(c3, 0.f);
            }
            *(float2*)(C + (size_t)row*M + col)     = make_float2(c0, c1);
            *(float2*)(C + (size_t)(row+8)*M + col) = make_float2(c2, c3);
        }
    }
}

// ---------------- causal attention per (b,e,h): reads packed QKV ------------------
__global__ __launch_bounds__(128) void attn_kernel()
{
    int qc  = blockIdx.x;
    int beh = blockIdx.y;
    int h = beh & 7;
    int e = (beh >> 3) & 3;
    int b = beh >> 5;
    int t = threadIdx.x;
    int s = qc*128 + t;

    __shared__ float4 Ks[64][16];
    __shared__ float4 Vs[64][16];

    const size_t qbase = (size_t)e*3*D_ + (size_t)h*HD_;
    const float* qp = g_qkv + (size_t)(s*B_+b)*QKVM_ + qbase;

    float4 q4[16];
    #pragma unroll
    for (int i = 0; i < 16; i++) q4[i] = *(const float4*)(qp + i*4);

    float4 a4[16];
    #pragma unroll
    for (int i = 0; i < 16; i++) a4[i] = make_float4(0.f, 0.f, 0.f, 0.f);
    float m = NEGINF_, lsum = 0.f;

    int nkc = 2*qc + 2;
    for (int kc = 0; kc < nkc; kc++) {
        int j0 = kc * 64;
        __syncthreads();
        #pragma unroll
        for (int i = 0; i < 8; i++) {
            int idx = t + i*128;
            int j = idx >> 4;
            int cc = idx & 15;
            size_t off = (size_t)((j0+j)*B_ + b)*QKVM_ + qbase + cc*4;
            Ks[j][cc] = *(const float4*)(g_qkv + off + D_);
            Vs[j][cc] = *(const float4*)(g_qkv + off + 2*D_);
        }
        __syncthreads();
        for (int sub = 0; sub < 4; sub++) {
            int j0s = j0 + sub*16;
            if (j0s > s) break;
            float sc[16];
            #pragma unroll
            for (int jj = 0; jj < 16; jj++) {
                int j = sub*16 + jj;
                float s0=0.f, s1=0.f, s2=0.f, s3=0.f;
                #pragma unroll
                for (int i = 0; i < 16; i++) {
                    float4 kk = Ks[j][i];
                    s0 = fmaf(q4[i].x, kk.x, s0);
                    s1 = fmaf(q4[i].y, kk.y, s1);
                    s2 = fmaf(q4[i].z, kk.z, s2);
                    s3 = fmaf(q4[i].w, kk.w, s3);
                }
                float v = ((s0+s1)+(s2+s3)) * 0.125f;
                sc[jj] = (j0s + jj <= s) ? v : NEGINF_;
            }
            float cm = sc[0];
            #pragma unroll
            for (int jj = 1; jj < 16; jj++) cm = fmaxf(cm, sc[jj]);
            float newm = fmaxf(m, cm);
            float alpha = __expf(m - newm);
            lsum *= alpha;
            #pragma unroll
            for (int i = 0; i < 16; i++) {
                a4[i].x *= alpha; a4[i].y *= alpha;
                a4[i].z *= alpha; a4[i].w *= alpha;
            }
            m = newm;
            #pragma unroll
            for (int jj = 0; jj < 16; jj++) {
                float p = __expf(sc[jj] - m);
                lsum += p;
                int j = sub*16 + jj;
                #pragma unroll
                for (int i = 0; i < 16; i++) {
                    float4 vv = Vs[j][i];
                    a4[i].x = fmaf(p, vv.x, a4[i].x);
                    a4[i].y = fmaf(p, vv.y, a4[i].y);
                    a4[i].z = fmaf(p, vv.z, a4[i].z);
                    a4[i].w = fmaf(p, vv.w, a4[i].w);
                }
            }
        }
    }
    float inv = 1.f / lsum;
    float* op = g_ctx + (size_t)e*N_*D_ + (size_t)h*HD_ + (size_t)(s*B_+b)*D_;
    #pragma unroll
    for (int i = 0; i < 16; i++) {
        float4 o = make_float4(a4[i].x*inv, a4[i].y*inv, a4[i].z*inv, a4[i].w*inv);
        *(float4*)(op + i*4) = o;
    }
}

// ---------------- block sum helper ----------------
__device__ __forceinline__ float blocksum128(float v)
{
    __shared__ float sh[4];
    #pragma unroll
    for (int o = 16; o > 0; o >>= 1) v += __shfl_down_sync(0xffffffffu, v, o);
    __syncthreads();
    if ((threadIdx.x & 31) == 0) sh[threadIdx.x >> 5] = v;
    __syncthreads();
    return sh[0] + sh[1] + sh[2] + sh[3];
}

// ---------------- fused: x = LN2(LN1(x + sum_e gate*eo)) ----------------
__global__ void comb_ln12_kernel(const float* __restrict__ g1, const float* __restrict__ b1v,
                                 const float* __restrict__ g2, const float* __restrict__ b2v)
{
    int n = blockIdx.x;
    int t = threadIdx.x;
    int idx = n*128 + t;
    const float4* eo = (const float4*)g_q;
    const int z = N_*D_/4;
    float ga0 = g_gate[n*4+0];
    float ga1 = g_gate[n*4+1];
    float ga2 = g_gate[n*4+2];
    float ga3 = g_gate[n*4+3];
    float4 v0 = eo[idx];
    float4 v1 = eo[z+idx];
    float4 v2 = eo[2*z+idx];
    float4 v3 = eo[3*z+idx];
    float4 xr = ((const float4*)g_x)[idx];
    float c0 = xr.x + ga0*v0.x + ga1*v1.x + ga2*v2.x + ga3*v3.x;
    float c1 = xr.y + ga0*v0.y + ga1*v1.y + ga2*v2.y + ga3*v3.y;
    float c2 = xr.z + ga0*v0.z + ga1*v1.z + ga2*v2.z + ga3*v3.z;
    float c3 = xr.w + ga0*v0.w + ga1*v1.w + ga2*v2.w + ga3*v3.w;

    float mean = blocksum128(c0+c1+c2+c3) * (1.f/D_);
    float d0 = c0-mean, d1 = c1-mean, d2 = c2-mean, d3 = c3-mean;
    float var = blocksum128(d0*d0 + d1*d1 + d2*d2 + d3*d3) * (1.f/D_);
    float rstd = rsqrtf(var + EPS_);
    float4 gg1 = ((const float4*)g1)[t];
    float4 bb1 = ((const float4*)b1v)[t];
    float y0 = d0*rstd*gg1.x + bb1.x;
    float y1 = d1*rstd*gg1.y + bb1.y;
    float y2 = d2*rstd*gg1.z + bb1.z;
    float y3 = d3*rstd*gg1.w + bb1.w;

    float mean2 = blocksum128(y0+y1+y2+y3) * (1.f/D_);
    float e0 = y0-mean2, e1 = y1-mean2, e2 = y2-mean2, e3 = y3-mean2;
    float var2 = blocksum128(e0*e0 + e1*e1 + e2*e2 + e3*e3) * (1.f/D_);
    float rstd2 = rsqrtf(var2 + EPS_);
    float4 gg2 = ((const float4*)g2)[t];
    float4 bb2 = ((const float4*)b2v)[t];
    float4 o;
    o.x = e0*rstd2*gg2.x + bb2.x;
    o.y = e1*rstd2*gg2.y + bb2.y;
    o.z = e2*rstd2*gg2.z + bb2.z;
    o.w = e3*rstd2*gg2.w + bb2.w;
    ((float4*)g_x)[idx] = o;
}

// ---------------- LayerNorm (residual add) ----------------
__global__ void ln_kernel(const float* __restrict__ xin, const float* __restrict__ res,
                          const float* __restrict__ g, const float* __restrict__ bb,
                          float* __restrict__ out)
{
    int n = blockIdx.x;
    int t = threadIdx.x;
    float4 v = ((const float4*)(xin + (size_t)n*D_))[t];
    if (res) {
        float4 r = ((const float4*)(res + (size_t)n*D_))[t];
        v.x += r.x; v.y += r.y; v.z += r.z; v.w += r.w;
    }
    float mean = blocksum128(v.x+v.y+v.z+v.w) * (1.f/D_);
    float d0 = v.x-mean, d1 = v.y-mean, d2 = v.z-mean, d3 = v.w-mean;
    float var = blocksum128(d0*d0 + d1*d1 + d2*d2 + d3*d3) * (1.f/D_);
    float rstd = rsqrtf(var + EPS_);
    float4 gg = ((const float4*)g)[t];
    float4 bv = ((const float4*)bb)[t];
    float4 o;
    o.x = d0*rstd*gg.x + bv.x;
    o.y = d1*rstd*gg.y + bv.y;
    o.z = d2*rstd*gg.z + bv.z;
    o.w = d3*rstd*gg.w + bv.w;
    ((float4*)(out + (size_t)n*D_))[t] = o;
}

// ---------------- in-place log_softmax over V per row (FMA-pipe exp) --------------
__global__ void lsm_kernel(float* __restrict__ out)
{
    __shared__ float sh[8];
    int n = blockIdx.x;
    int t = threadIdx.x;
    float4* row4 = (float4*)(out + (size_t)n*V_);
    const int NV4 = V_/4;

    float mx = NEGINF_;
    for (int i = t; i < NV4; i += 256) {
        float4 v = row4[i];
        mx = fmaxf(mx, fmaxf(fmaxf(v.x, v.y), fmaxf(v.z, v.w)));
    }
    #pragma unroll
    for (int o = 16; o > 0; o >>= 1) mx = fmaxf(mx, __shfl_xor_sync(0xffffffffu, mx, o));
    if ((t & 31) == 0) sh[t >> 5] = mx;
    __syncthreads();
    mx = fmaxf(fmaxf(fmaxf(sh[0],sh[1]), fmaxf(sh[2],sh[3])),
               fmaxf(fmaxf(sh[4],sh[5]), fmaxf(sh[6],sh[7])));

    float sum = 0.f;
    for (int i = t; i < NV4; i += 256) {
        float4 v = row4[i];
        sum += fexp(v.x - mx) + fexp(v.y - mx) + fexp(v.z - mx) + fexp(v.w - mx);
    }
    #pragma unroll
    for (int o = 16; o > 0; o >>= 1) sum += __shfl_xor_sync(0xffffffffu, sum, o);
    __syncthreads();
    if ((t & 31) == 0) sh[t >> 5] = sum;
    __syncthreads();
    sum = ((sh[0]+sh[1]) + (sh[2]+sh[3])) + ((sh[4]+sh[5]) + (sh[6]+sh[7]));
    float lse = mx + logf(sum);

    for (int i = t; i < NV4; i += 256) {
        float4 v = row4[i];
        v.x -= lse; v.y -= lse; v.z -= lse; v.w -= lse;
        row4[i] = v;
    }
}

__global__ void write_aux_kernel(float* __restrict__ out)
{
    out[(size_t)N_*V_] = g_aux;
}

// ---------------- host orchestration ----------------
extern "C" void kernel_launch(void* const* d_in, const int* in_sizes, int n_in,
                              void* d_out, int out_size)
{
    (void)in_sizes; (void)n_in;
    const int*   src    = (const int*)  d_in[1];
    const float* emb    = (const float*)d_in[2];
    const float* gate_w = (const float*)d_in[3];
    const float* gate_b = (const float*)d_in[4];
    const float* wq     = (const float*)d_in[5];
    const float* wk     = (const float*)d_in[6];
    const float* wv     = (const float*)d_in[7];
    const float* wo     = (const float*)d_in[8];
    const float* bq     = (const float*)d_in[9];
    const float* bk     = (const float*)d_in[10];
    const float* bv     = (const float*)d_in[11];
    const float* bo     = (const float*)d_in[12];
    const float* w1     = (const float*)d_in[13];
    const float* b1     = (const float*)d_in[14];
    const float* w2     = (const float*)d_in[15];
    const float* b2     = (const float*)d_in[16];
    const float* ln1_g  = (const float*)d_in[17];
    const float* ln1_b  = (const float*)d_in[18];
    const float* ln2_g  = (const float*)d_in[19];
    const float* ln2_b  = (const float*)d_in[20];
    const float* ln3_g  = (const float*)d_in[21];
    const float* ln3_b  = (const float*)d_in[22];
    const float* lnf_g  = (const float*)d_in[23];
    const float* lnf_b  = (const float*)d_in[24];
    const float* out_w  = (const float*)d_in[25];
    const float* out_b  = (const float*)d_in[26];
    float* out = (float*)d_out;

    float *px, *ptmp, *pqkv, *peo, *pctx, *ph, *pbqkv;
    cudaGetSymbolAddress((void**)&px,    g_x);
    cudaGetSymbolAddress((void**)&ptmp,  g_tmp);
    cudaGetSymbolAddress((void**)&pqkv,  g_qkv);
    cudaGetSymbolAddress((void**)&peo,   g_q);
    cudaGetSymbolAddress((void**)&pctx,  g_ctx);
    cudaGetSymbolAddress((void**)&ph,    g_h);
    cudaGetSymbolAddress((void**)&pbqkv, g_bqkv);

    __nv_bfloat16 *pqkv_h, *pqkv_l, *pwo_h, *pwo_l;
    __nv_bfloat16 *pw1_h, *pw1_l, *pw2_h, *pw2_l, *pow_h, *pow_l;
    cudaGetSymbolAddress((void**)&pqkv_h, g_wqkv_h);
    cudaGetSymbolAddress((void**)&pqkv_l, g_wqkv_l);
    cudaGetSymbolAddress((void**)&pwo_h, g_wo_h);
    cudaGetSymbolAddress((void**)&pwo_l, g_wo_l);
    cudaGetSymbolAddress((void**)&pw1_h, g_w1_h);
    cudaGetSymbolAddress((void**)&pw1_l, g_w1_l);
    cudaGetSymbolAddress((void**)&pw2_h, g_w2_h);
    cudaGetSymbolAddress((void**)&pw2_l, g_w2_l);
    cudaGetSymbolAddress((void**)&pow_h, g_ow_h);
    cudaGetSymbolAddress((void**)&pow_l, g_ow_l);

    cudaFuncSetAttribute(gemm_mma, cudaFuncAttributeMaxDynamicSharedMemorySize, GSMEM);

    size_t dd = (size_t)D_*D_;
    size_t nd = (size_t)N_*D_;

    // convert into packed QKV weight layout: per (l,e) block of 3*D rows (q,k,v)
    convert_w<<<dim3(D_/32, D_/32, L_*E_), 256>>>(wq, pqkv_h,          pqkv_l,          D_, D_, dd, 3*dd);
    convert_w<<<dim3(D_/32, D_/32, L_*E_), 256>>>(wk, pqkv_h + dd,     pqkv_l + dd,     D_, D_, dd, 3*dd);
    convert_w<<<dim3(D_/32, D_/32, L_*E_), 256>>>(wv, pqkv_h + 2*dd,   pqkv_l + 2*dd,   D_, D_, dd, 3*dd);
    convert_w<<<dim3(D_/32, D_/32, L_*E_), 256>>>(wo, pwo_h, pwo_l, D_, D_, dd, dd);
    convert_w<<<dim3(FF_/32, D_/32, L_), 256>>>(w1, pw1_h, pw1_l, D_, FF_, (size_t)D_*FF_, (size_t)D_*FF_);
    convert_w<<<dim3(D_/32, FF_/32, L_), 256>>>(w2, pw2_h, pw2_l, FF_, D_, (size_t)FF_*D_, (size_t)FF_*D_);
    convert_w<<<dim3(V_/32, D_/32, 1), 256>>>(out_w, pow_h, pow_l, D_, V_, 0, 0);
    pack_bias<<<(L_*QKVM_)/256, 256>>>(bq, bk, bv);

    embed_kernel<<<N_, 128>>>(src, emb);

    for (int l = 0; l < L_; l++) {
        gate_kernel<<<N_, 128>>>(gate_w + (size_t)l*D_*E_, gate_b + (size_t)l*E_);
        aux_kernel<<<1, 256>>>();

        size_t qkwoff = (size_t)l*E_*3*dd;
        size_t woff = (size_t)l*E_*dd;
        size_t boff = (size_t)l*E_*D_;

        // fused QKV for all experts: one GEMM, M = 6144
        gemm_mma<<<dim3(QKVM_/64, N_/128), 256, GSMEM>>>(
            px, pqkv_h + qkwoff, pqkv_l + qkwoff, pbqkv + (size_t)l*QKVM_, pqkv,
            N_, D_, QKVM_, 0, 0, 0, 0, 0);

        attn_kernel<<<dim3(4, B_*E_*H_), 128>>>();

        gemm_mma<<<dim3(D_/64, N_/128, E_), 256, GSMEM>>>(
            pctx, pwo_h + woff, pwo_l + woff, bo + boff, peo,
            N_, D_, D_, nd, dd, D_, nd, 0);

        comb_ln12_kernel<<<N_, 128>>>(ln1_g + (size_t)l*D_, ln1_b + (size_t)l*D_,
                                      ln2_g + (size_t)l*D_, ln2_b + (size_t)l*D_);

        gemm_mma<<<dim3(FF_/64, N_/128), 256, GSMEM>>>(
            px, pw1_h + (size_t)l*D_*FF_, pw1_l + (size_t)l*D_*FF_,
            b1 + (size_t)l*FF_, ph, N_, D_, FF_, 0, 0, 0, 0, 1);
        gemm_mma<<<dim3(D_/64, N_/128), 256, GSMEM>>>(
            ph, pw2_h + (size_t)l*FF_*D_, pw2_l + (size_t)l*FF_*D_,
            b2 + (size_t)l*D_, ptmp, N_, FF_, D_, 0, 0, 0, 0, 0);

        ln_kernel<<<N_, 128>>>(px, ptmp, ln3_g + (size_t)l*D_, ln3_b + (size_t)l*D_, px);
    }

    ln_kernel<<<N_, 128>>>(px, (const float*)0, lnf_g, lnf_b, px);

    gemm_mma<<<dim3(V_/64, N_/128), 256, GSMEM>>>(
        px, pow_h, pow_l, out_b, out, N_, D_, V_, 0, 0, 0, 0, 0);
    lsm_kernel<<<N_, 256>>>(out);

    if (out_size > N_*V_) {
        write_aux_kernel<<<1, 1>>>(out);
    }
}